// round 11
// baseline (speedup 1.0000x reference)
#include <cuda_runtime.h>
#include <cuda_fp16.h>
#include <cuda_pipeline.h>
#include <mma.h>
#include <math.h>
#include <float.h>

#define BB 32
#define NTOK 576
#define DD 1024
#define KSEL 128

using namespace nvcuda;

// Scratch (no cudaMalloc allowed)
__device__ __half g_h[BB * NTOK * DD];    // fp16 hi part of normalized feats
__device__ __half g_l[BB * NTOK * DD];    // fp16 lo part, scaled by 2048
__device__ float  g_sim[BB * NTOK * NTOK];
__device__ int    g_sorted[BB * KSEL];
__device__ int    g_order[BB * KSEL];

// ---------------------------------------------------------------------------
// K1: row-normalize feats = hidden[:,1:,:], split into fp16 hi/lo
// ---------------------------------------------------------------------------
__global__ __launch_bounds__(256) void k_normsplit(const float* __restrict__ hidden) {
    int n = blockIdx.x, b = blockIdx.y;
    const float4* src = (const float4*)(hidden + ((size_t)b * (NTOK + 1) + n + 1) * DD);
    int tid = threadIdx.x;
    float4 x = src[tid];
    float s = x.x * x.x + x.y * x.y + x.z * x.z + x.w * x.w;
    #pragma unroll
    for (int o = 16; o; o >>= 1) s += __shfl_xor_sync(0xffffffffu, s, o);
    __shared__ float sw[8];
    __shared__ float snrm;
    if ((tid & 31) == 0) sw[tid >> 5] = s;
    __syncthreads();
    if (tid == 0) {
        float t = 0.f;
        #pragma unroll
        for (int i = 0; i < 8; i++) t += sw[i];
        snrm = __fsqrt_rn(t);
    }
    __syncthreads();
    float nr = snrm;
    float y0 = __fdiv_rn(x.x, nr);
    float y1 = __fdiv_rn(x.y, nr);
    float y2 = __fdiv_rn(x.z, nr);
    float y3 = __fdiv_rn(x.w, nr);
    __half h0 = __float2half_rn(y0);
    __half h1 = __float2half_rn(y1);
    __half h2 = __float2half_rn(y2);
    __half h3 = __float2half_rn(y3);
    __half l0 = __float2half_rn(__fmul_rn(__fsub_rn(y0, __half2float(h0)), 2048.0f));
    __half l1 = __float2half_rn(__fmul_rn(__fsub_rn(y1, __half2float(h1)), 2048.0f));
    __half l2 = __float2half_rn(__fmul_rn(__fsub_rn(y2, __half2float(h2)), 2048.0f));
    __half l3 = __float2half_rn(__fmul_rn(__fsub_rn(y3, __half2float(h3)), 2048.0f));
    size_t base = ((size_t)b * NTOK + n) * DD;
    __half2* H2 = (__half2*)(g_h + base);
    __half2* L2 = (__half2*)(g_l + base);
    H2[tid * 2 + 0] = __halves2half2(h0, h1);
    H2[tid * 2 + 1] = __halves2half2(h2, h3);
    L2[tid * 2 + 0] = __halves2half2(l0, l1);
    L2[tid * 2 + 1] = __halves2half2(l2, l3);
}

// ---------------------------------------------------------------------------
// K2: sim[b] = H@H^T + 2^-11 (H@L^T + L@H^T), WMMA fp16 -> fp32 (no inline asm).
// CTA tile 96x96 (576 = 6*96), symmetric ti<=tj + mirror store.
// 6 warps (3x2), warp tile 32x48 = 2x3 wmma 16x16x16 tiles.
// k-chunk 16, double-buffered via __pipeline_memcpy_async.
// ---------------------------------------------------------------------------
// smem layout per stage: 4 arrays (AH, AL, BH, BL), each 96 rows x 24 halves
#define SARR 2304   // 96*24 halves per array
#define SLD  24     // smem leading dim in halves

__device__ __forceinline__ void load_chunk16(__half* sb,
                                             const __half* Hb, const __half* Lb,
                                             int i0, int j0, int k0, int tid) {
    int row = tid >> 1;
    int seg = tid & 1;
    size_t goffA = (size_t)(i0 + row) * DD + k0 + seg * 8;
    size_t goffB = (size_t)(j0 + row) * DD + k0 + seg * 8;
    int soff = row * SLD + seg * 8;
    __pipeline_memcpy_async(sb + 0 * SARR + soff, Hb + goffA, 16);
    __pipeline_memcpy_async(sb + 1 * SARR + soff, Lb + goffA, 16);
    __pipeline_memcpy_async(sb + 2 * SARR + soff, Hb + goffB, 16);
    __pipeline_memcpy_async(sb + 3 * SARR + soff, Lb + goffB, 16);
    __pipeline_commit();
}

__global__ __launch_bounds__(192, 1) void k_simgemm_tc() {
    int b = blockIdx.y;
    int t = blockIdx.x;                 // 0..20 -> (ti<=tj) over 6x6 tiles
    int ti = 0, rem = 6;
    while (t >= rem) { t -= rem; rem--; ti++; }
    int tj = ti + t;
    int i0 = ti * 96, j0 = tj * 96;

    const __half* Hb = g_h + (size_t)b * NTOK * DD;
    const __half* Lb = g_l + (size_t)b * NTOK * DD;
    float* C = g_sim + (size_t)b * NTOK * NTOK;

    __shared__ __half sm[2][4 * SARR];   // 2 stages x 4 arrays, 36864 bytes

    int tid = threadIdx.x;
    int warp = tid >> 5;
    int wm = (warp % 3) * 32;            // M offset within 96
    int wn = (warp / 3) * 48;            // N offset within 96

    wmma::fragment<wmma::accumulator, 16, 16, 16, float> acc0[2][3];
    wmma::fragment<wmma::accumulator, 16, 16, 16, float> acc1[2][3];
    #pragma unroll
    for (int mt = 0; mt < 2; mt++) {
        #pragma unroll
        for (int nt = 0; nt < 3; nt++) {
            wmma::fill_fragment(acc0[mt][nt], 0.0f);
            wmma::fill_fragment(acc1[mt][nt], 0.0f);
        }
    }

    load_chunk16(&sm[0][0], Hb, Lb, i0, j0, 0, tid);

    const int NCHUNK = DD / 16;   // 64
    for (int ck = 0; ck < NCHUNK; ck++) {
        int st = ck & 1;
        if (ck + 1 < NCHUNK) {
            load_chunk16(&sm[st ^ 1][0], Hb, Lb, i0, j0, (ck + 1) * 16, tid);
            __pipeline_wait_prior(1);
        } else {
            __pipeline_wait_prior(0);
        }
        __syncthreads();

        __half* base = &sm[st][0];
        wmma::fragment<wmma::matrix_a, 16, 16, 16, __half, wmma::row_major> aH[2], aL[2];
        wmma::fragment<wmma::matrix_b, 16, 16, 16, __half, wmma::col_major> bH[3], bL[3];
        #pragma unroll
        for (int mt = 0; mt < 2; mt++) {
            wmma::load_matrix_sync(aH[mt], base + 0 * SARR + (wm + mt * 16) * SLD, SLD);
            wmma::load_matrix_sync(aL[mt], base + 1 * SARR + (wm + mt * 16) * SLD, SLD);
        }
        #pragma unroll
        for (int nt = 0; nt < 3; nt++) {
            wmma::load_matrix_sync(bH[nt], base + 2 * SARR + (wn + nt * 16) * SLD, SLD);
            wmma::load_matrix_sync(bL[nt], base + 3 * SARR + (wn + nt * 16) * SLD, SLD);
        }
        #pragma unroll
        for (int mt = 0; mt < 2; mt++) {
            #pragma unroll
            for (int nt = 0; nt < 3; nt++) {
                wmma::mma_sync(acc0[mt][nt], aH[mt], bH[nt], acc0[mt][nt]);
                wmma::mma_sync(acc1[mt][nt], aH[mt], bL[nt], acc1[mt][nt]);
                wmma::mma_sync(acc1[mt][nt], aL[mt], bH[nt], acc1[mt][nt]);
            }
        }
        __syncthreads();
    }

    const float S = 4.8828125e-4f;   // 2^-11
    #pragma unroll
    for (int mt = 0; mt < 2; mt++) {
        #pragma unroll
        for (int nt = 0; nt < 3; nt++) {
            #pragma unroll
            for (int e = 0; e < acc0[mt][nt].num_elements; e++) {
                acc0[mt][nt].x[e] = acc0[mt][nt].x[e] + acc1[mt][nt].x[e] * S;
            }
            int r0 = i0 + wm + mt * 16;
            int c0 = j0 + wn + nt * 16;
            wmma::store_matrix_sync(&C[(size_t)r0 * NTOK + c0], acc0[mt][nt],
                                    NTOK, wmma::mem_row_major);
            if (ti != tj) {
                wmma::store_matrix_sync(&C[(size_t)c0 * NTOK + r0], acc0[mt][nt],
                                        NTOK, wmma::mem_col_major);
            }
        }
    }
}

// ---------------------------------------------------------------------------
// K3: greedy SCOPE selection, one CTA per batch, incremental gain updates.
// ---------------------------------------------------------------------------
__device__ __forceinline__ void kacc(float& s, float& c, float x) {
    float y = __fsub_rn(x, c);
    float t = __fadd_rn(s, y);
    c = __fsub_rn(__fsub_rn(t, s), y);
    s = t;
}

__global__ __launch_bounds__(NTOK) void k_greedy(const float* __restrict__ cls_attn) {
    int b = blockIdx.x;
    const float* sim = g_sim + (size_t)b * NTOK * NTOK;
    int m = threadIdx.x;
    int w = m >> 5, lane = m & 31;

    __shared__ float s_curmax[NTOK];
    __shared__ float s_cls[NTOK];
    __shared__ unsigned char s_sel[NTOK];
    __shared__ short s_chidx[NTOK];
    __shared__ float s_chold[NTOK];
    __shared__ float s_chnew[NTOK];
    __shared__ int s_wcnt[18];
    __shared__ float s_rval[18];
    __shared__ int s_ridx[18];
    __shared__ int s_best;
    __shared__ int s_order[KSEL];

    s_cls[m] = cls_attn[b * NTOK + m];
    s_curmax[m] = 0.f;
    s_sel[m] = 0;

    float sum0 = 0.f, c0 = 0.f, sum1 = 0.f, c1 = 0.f;
    for (int n = 0; n < NTOK; n += 8) {
        float v[8];
        #pragma unroll
        for (int u = 0; u < 8; u++) v[u] = sim[(size_t)(n + u) * NTOK + m];
        #pragma unroll
        for (int u = 0; u < 8; u++) {
            float rl = fmaxf(v[u], 0.f);
            if (u & 1) kacc(sum1, c1, rl); else kacc(sum0, c0, rl);
        }
    }
    __syncthreads();

    for (int k = 0; k < KSEL; k++) {
        float g = __fadd_rn(__fsub_rn(sum0, c0), __fsub_rn(sum1, c1));
        float key = s_sel[m] ? -FLT_MAX : g * s_cls[m];
        float bv = key; int bi = m;
        #pragma unroll
        for (int o = 16; o; o >>= 1) {
            float ov = __shfl_down_sync(0xffffffffu, bv, o);
            int   oi = __shfl_down_sync(0xffffffffu, bi, o);
            if (ov > bv || (ov == bv && oi < bi)) { bv = ov; bi = oi; }
        }
        if (lane == 0) { s_rval[w] = bv; s_ridx[w] = bi; }
        __syncthreads();
        if (m < 32) {
            float rv = (m < 18) ? s_rval[m] : -FLT_MAX;
            int   ri = (m < 18) ? s_ridx[m] : 0x7fffffff;
            #pragma unroll
            for (int o = 16; o; o >>= 1) {
                float ov = __shfl_down_sync(0xffffffffu, rv, o);
                int   oi = __shfl_down_sync(0xffffffffu, ri, o);
                if (ov > rv || (ov == rv && oi < ri)) { rv = ov; ri = oi; }
            }
            if (m == 0) { s_best = ri; s_order[k] = ri; s_sel[ri] = 1; }
        }
        __syncthreads();
        int best = s_best;

        float old = s_curmax[m];
        float nv = sim[(size_t)best * NTOK + m];
        bool ch = nv > old;
        unsigned bmask = __ballot_sync(0xffffffffu, ch);
        if (lane == 0) s_wcnt[w] = __popc(bmask);
        if (ch) s_curmax[m] = nv;
        __syncthreads();
        int base = 0, tot = 0;
        #pragma unroll
        for (int i = 0; i < 18; i++) { int cc = s_wcnt[i]; if (i < w) base += cc; tot += cc; }
        if (ch) {
            int pos = base + __popc(bmask & ((1u << lane) - 1u));
            s_chidx[pos] = (short)m;
            s_chold[pos] = old;
            s_chnew[pos] = nv;
        }
        __syncthreads();

        int r = 0;
        while (r + 4 <= tot) {
            int n0 = s_chidx[r + 0], n1 = s_chidx[r + 1], n2 = s_chidx[r + 2], n3 = s_chidx[r + 3];
            float o0 = s_chold[r + 0], o1 = s_chold[r + 1], o2 = s_chold[r + 2], o3 = s_chold[r + 3];
            float e0 = s_chnew[r + 0], e1 = s_chnew[r + 1], e2 = s_chnew[r + 2], e3 = s_chnew[r + 3];
            float v0 = sim[(size_t)n0 * NTOK + m];
            float v1 = sim[(size_t)n1 * NTOK + m];
            float v2 = sim[(size_t)n2 * NTOK + m];
            float v3 = sim[(size_t)n3 * NTOK + m];
            float d0 = fmaxf(__fsub_rn(fminf(v0, e0), o0), 0.f);
            float d1 = fmaxf(__fsub_rn(fminf(v1, e1), o1), 0.f);
            float d2 = fmaxf(__fsub_rn(fminf(v2, e2), o2), 0.f);
            float d3 = fmaxf(__fsub_rn(fminf(v3, e3), o3), 0.f);
            kacc(sum0, c0, -d0); kacc(sum1, c1, -d1);
            kacc(sum0, c0, -d2); kacc(sum1, c1, -d3);
            r += 4;
        }
        while (r < tot) {
            int nn = s_chidx[r];
            float oo = s_chold[r], ee = s_chnew[r];
            float vv = sim[(size_t)nn * NTOK + m];
            float dd = fmaxf(__fsub_rn(fminf(vv, ee), oo), 0.f);
            kacc(sum0, c0, -dd);
            r += 1;
        }
        __syncthreads();
    }

    bool f = s_sel[m] != 0;
    unsigned fm = __ballot_sync(0xffffffffu, f);
    if (lane == 0) s_wcnt[w] = __popc(fm);
    __syncthreads();
    int base = 0;
    #pragma unroll
    for (int i = 0; i < 18; i++) if (i < w) base += s_wcnt[i];
    if (f) g_sorted[b * KSEL + base + __popc(fm & ((1u << lane) - 1u))] = m + 1;
    if (m < KSEL) g_order[b * KSEL + m] = s_order[m] + 1;
}

// ---------------------------------------------------------------------------
// K4: gather dominant tokens + write selection-order indices (as float)
// ---------------------------------------------------------------------------
__global__ __launch_bounds__(128) void k_gather(const float* __restrict__ hidden,
                                                float* __restrict__ out_tok,
                                                float* __restrict__ out_idx,
                                                int write_idx) {
    int k = blockIdx.x, b = blockIdx.y;
    int gi = g_sorted[b * KSEL + k];
    const float4* src = (const float4*)(hidden + ((size_t)b * (NTOK + 1) + gi) * DD);
    float4* dst = (float4*)(out_tok + ((size_t)b * KSEL + k) * DD);
    int tid = threadIdx.x;
    dst[tid] = src[tid];
    dst[tid + 128] = src[tid + 128];
    if (write_idx && k == 0) out_idx[b * KSEL + tid] = (float)g_order[b * KSEL + tid];
}

// ---------------------------------------------------------------------------
extern "C" void kernel_launch(void* const* d_in, const int* in_sizes, int n_in,
                              void* d_out, int out_size) {
    const float* hidden = (const float*)d_in[0];   // [32, 577, 1024] f32
    const float* cls    = (const float*)d_in[1];   // [32, 576] f32
    float* out = (float*)d_out;

    k_normsplit<<<dim3(NTOK, BB), 256>>>(hidden);
    k_simgemm_tc<<<dim3(21, BB), 192>>>();
    k_greedy<<<BB, NTOK>>>(cls);

    const int tok_elems = BB * KSEL * DD;
    int write_idx = (out_size >= tok_elems + BB * KSEL) ? 1 : 0;
    k_gather<<<dim3(KSEL, BB), 128>>>(hidden, out, out + tok_elems, write_idx);
}

// round 12
// speedup vs baseline: 1.0024x; 1.0024x over previous
#include <cuda_runtime.h>
#include <cuda_fp16.h>
#include <cuda_pipeline.h>
#include <mma.h>
#include <math.h>
#include <float.h>

#define BB 32
#define NTOK 576
#define DD 1024
#define KSEL 128

using namespace nvcuda;

// Scratch (no cudaMalloc allowed)
__device__ __half g_h[BB * NTOK * DD];    // fp16 hi part of normalized feats
__device__ __half g_l[BB * NTOK * DD];    // fp16 lo part, scaled by 2048
__device__ float  g_sim[BB * NTOK * NTOK];
__device__ int    g_sorted[BB * KSEL];
__device__ int    g_order[BB * KSEL];

// ---------------------------------------------------------------------------
// K1: row-normalize feats = hidden[:,1:,:], split into fp16 hi/lo
// ---------------------------------------------------------------------------
__global__ __launch_bounds__(256) void k_normsplit(const float* __restrict__ hidden) {
    int n = blockIdx.x, b = blockIdx.y;
    const float4* src = (const float4*)(hidden + ((size_t)b * (NTOK + 1) + n + 1) * DD);
    int tid = threadIdx.x;
    float4 x = src[tid];
    float s = x.x * x.x + x.y * x.y + x.z * x.z + x.w * x.w;
    #pragma unroll
    for (int o = 16; o; o >>= 1) s += __shfl_xor_sync(0xffffffffu, s, o);
    __shared__ float sw[8];
    __shared__ float snrm;
    if ((tid & 31) == 0) sw[tid >> 5] = s;
    __syncthreads();
    if (tid == 0) {
        float t = 0.f;
        #pragma unroll
        for (int i = 0; i < 8; i++) t += sw[i];
        snrm = __fsqrt_rn(t);
    }
    __syncthreads();
    float nr = snrm;
    float y0 = __fdiv_rn(x.x, nr);
    float y1 = __fdiv_rn(x.y, nr);
    float y2 = __fdiv_rn(x.z, nr);
    float y3 = __fdiv_rn(x.w, nr);
    __half h0 = __float2half_rn(y0);
    __half h1 = __float2half_rn(y1);
    __half h2 = __float2half_rn(y2);
    __half h3 = __float2half_rn(y3);
    __half l0 = __float2half_rn(__fmul_rn(__fsub_rn(y0, __half2float(h0)), 2048.0f));
    __half l1 = __float2half_rn(__fmul_rn(__fsub_rn(y1, __half2float(h1)), 2048.0f));
    __half l2 = __float2half_rn(__fmul_rn(__fsub_rn(y2, __half2float(h2)), 2048.0f));
    __half l3 = __float2half_rn(__fmul_rn(__fsub_rn(y3, __half2float(h3)), 2048.0f));
    size_t base = ((size_t)b * NTOK + n) * DD;
    __half2* H2 = (__half2*)(g_h + base);
    __half2* L2 = (__half2*)(g_l + base);
    H2[tid * 2 + 0] = __halves2half2(h0, h1);
    H2[tid * 2 + 1] = __halves2half2(h2, h3);
    L2[tid * 2 + 0] = __halves2half2(l0, l1);
    L2[tid * 2 + 1] = __halves2half2(l2, l3);
}

// ---------------------------------------------------------------------------
// K2: sim[b] = H@H^T + 2^-11 (H@L^T + L@H^T), WMMA fp16 -> fp32 (no inline asm).
// CTA tile 96x96 (576 = 6*96), symmetric ti<=tj + mirror store.
// 6 warps (3x2), warp tile 32x48 = 2x3 wmma 16x16x16 tiles.
// k-chunk 16, double-buffered via __pipeline_memcpy_async.
// ---------------------------------------------------------------------------
// smem layout per stage: 4 arrays (AH, AL, BH, BL), each 96 rows x 24 halves
#define SARR 2304   // 96*24 halves per array
#define SLD  24     // smem leading dim in halves

__device__ __forceinline__ void load_chunk16(__half* sb,
                                             const __half* Hb, const __half* Lb,
                                             int i0, int j0, int k0, int tid) {
    int row = tid >> 1;
    int seg = tid & 1;
    size_t goffA = (size_t)(i0 + row) * DD + k0 + seg * 8;
    size_t goffB = (size_t)(j0 + row) * DD + k0 + seg * 8;
    int soff = row * SLD + seg * 8;
    __pipeline_memcpy_async(sb + 0 * SARR + soff, Hb + goffA, 16);
    __pipeline_memcpy_async(sb + 1 * SARR + soff, Lb + goffA, 16);
    __pipeline_memcpy_async(sb + 2 * SARR + soff, Hb + goffB, 16);
    __pipeline_memcpy_async(sb + 3 * SARR + soff, Lb + goffB, 16);
    __pipeline_commit();
}

__global__ __launch_bounds__(192, 1) void k_simgemm_tc() {
    int b = blockIdx.y;
    int t = blockIdx.x;                 // 0..20 -> (ti<=tj) over 6x6 tiles
    int ti = 0, rem = 6;
    while (t >= rem) { t -= rem; rem--; ti++; }
    int tj = ti + t;
    int i0 = ti * 96, j0 = tj * 96;

    const __half* Hb = g_h + (size_t)b * NTOK * DD;
    const __half* Lb = g_l + (size_t)b * NTOK * DD;
    float* C = g_sim + (size_t)b * NTOK * NTOK;

    __shared__ __half sm[2][4 * SARR];   // 2 stages x 4 arrays, 36864 bytes

    int tid = threadIdx.x;
    int warp = tid >> 5;
    int wm = (warp % 3) * 32;            // M offset within 96
    int wn = (warp / 3) * 48;            // N offset within 96

    wmma::fragment<wmma::accumulator, 16, 16, 16, float> acc0[2][3];
    wmma::fragment<wmma::accumulator, 16, 16, 16, float> acc1[2][3];
    #pragma unroll
    for (int mt = 0; mt < 2; mt++) {
        #pragma unroll
        for (int nt = 0; nt < 3; nt++) {
            wmma::fill_fragment(acc0[mt][nt], 0.0f);
            wmma::fill_fragment(acc1[mt][nt], 0.0f);
        }
    }

    load_chunk16(&sm[0][0], Hb, Lb, i0, j0, 0, tid);

    const int NCHUNK = DD / 16;   // 64
    for (int ck = 0; ck < NCHUNK; ck++) {
        int st = ck & 1;
        if (ck + 1 < NCHUNK) {
            load_chunk16(&sm[st ^ 1][0], Hb, Lb, i0, j0, (ck + 1) * 16, tid);
            __pipeline_wait_prior(1);
        } else {
            __pipeline_wait_prior(0);
        }
        __syncthreads();

        __half* base = &sm[st][0];
        wmma::fragment<wmma::matrix_a, 16, 16, 16, __half, wmma::row_major> aH[2], aL[2];
        wmma::fragment<wmma::matrix_b, 16, 16, 16, __half, wmma::col_major> bH[3], bL[3];
        #pragma unroll
        for (int mt = 0; mt < 2; mt++) {
            wmma::load_matrix_sync(aH[mt], base + 0 * SARR + (wm + mt * 16) * SLD, SLD);
            wmma::load_matrix_sync(aL[mt], base + 1 * SARR + (wm + mt * 16) * SLD, SLD);
        }
        #pragma unroll
        for (int nt = 0; nt < 3; nt++) {
            wmma::load_matrix_sync(bH[nt], base + 2 * SARR + (wn + nt * 16) * SLD, SLD);
            wmma::load_matrix_sync(bL[nt], base + 3 * SARR + (wn + nt * 16) * SLD, SLD);
        }
        #pragma unroll
        for (int mt = 0; mt < 2; mt++) {
            #pragma unroll
            for (int nt = 0; nt < 3; nt++) {
                wmma::mma_sync(acc0[mt][nt], aH[mt], bH[nt], acc0[mt][nt]);
                wmma::mma_sync(acc1[mt][nt], aH[mt], bL[nt], acc1[mt][nt]);
                wmma::mma_sync(acc1[mt][nt], aL[mt], bH[nt], acc1[mt][nt]);
            }
        }
        __syncthreads();
    }

    const float S = 4.8828125e-4f;   // 2^-11
    #pragma unroll
    for (int mt = 0; mt < 2; mt++) {
        #pragma unroll
        for (int nt = 0; nt < 3; nt++) {
            #pragma unroll
            for (int e = 0; e < acc0[mt][nt].num_elements; e++) {
                acc0[mt][nt].x[e] = acc0[mt][nt].x[e] + acc1[mt][nt].x[e] * S;
            }
            int r0 = i0 + wm + mt * 16;
            int c0 = j0 + wn + nt * 16;
            wmma::store_matrix_sync(&C[(size_t)r0 * NTOK + c0], acc0[mt][nt],
                                    NTOK, wmma::mem_row_major);
            if (ti != tj) {
                wmma::store_matrix_sync(&C[(size_t)c0 * NTOK + r0], acc0[mt][nt],
                                        NTOK, wmma::mem_col_major);
            }
        }
    }
}

// ---------------------------------------------------------------------------
// K3: greedy SCOPE selection, one CTA per batch, incremental gain updates.
// ---------------------------------------------------------------------------
__device__ __forceinline__ void kacc(float& s, float& c, float x) {
    float y = __fsub_rn(x, c);
    float t = __fadd_rn(s, y);
    c = __fsub_rn(__fsub_rn(t, s), y);
    s = t;
}

__global__ __launch_bounds__(NTOK) void k_greedy(const float* __restrict__ cls_attn) {
    int b = blockIdx.x;
    const float* sim = g_sim + (size_t)b * NTOK * NTOK;
    int m = threadIdx.x;
    int w = m >> 5, lane = m & 31;

    __shared__ float s_curmax[NTOK];
    __shared__ float s_cls[NTOK];
    __shared__ unsigned char s_sel[NTOK];
    __shared__ short s_chidx[NTOK];
    __shared__ float s_chold[NTOK];
    __shared__ float s_chnew[NTOK];
    __shared__ int s_wcnt[18];
    __shared__ float s_rval[18];
    __shared__ int s_ridx[18];
    __shared__ int s_best;
    __shared__ int s_order[KSEL];

    s_cls[m] = cls_attn[b * NTOK + m];
    s_curmax[m] = 0.f;
    s_sel[m] = 0;

    float sum0 = 0.f, c0 = 0.f, sum1 = 0.f, c1 = 0.f;
    for (int n = 0; n < NTOK; n += 8) {
        float v[8];
        #pragma unroll
        for (int u = 0; u < 8; u++) v[u] = sim[(size_t)(n + u) * NTOK + m];
        #pragma unroll
        for (int u = 0; u < 8; u++) {
            float rl = fmaxf(v[u], 0.f);
            if (u & 1) kacc(sum1, c1, rl); else kacc(sum0, c0, rl);
        }
    }
    __syncthreads();

    for (int k = 0; k < KSEL; k++) {
        float g = __fadd_rn(__fsub_rn(sum0, c0), __fsub_rn(sum1, c1));
        float key = s_sel[m] ? -FLT_MAX : g * s_cls[m];
        float bv = key; int bi = m;
        #pragma unroll
        for (int o = 16; o; o >>= 1) {
            float ov = __shfl_down_sync(0xffffffffu, bv, o);
            int   oi = __shfl_down_sync(0xffffffffu, bi, o);
            if (ov > bv || (ov == bv && oi < bi)) { bv = ov; bi = oi; }
        }
        if (lane == 0) { s_rval[w] = bv; s_ridx[w] = bi; }
        __syncthreads();
        if (m < 32) {
            float rv = (m < 18) ? s_rval[m] : -FLT_MAX;
            int   ri = (m < 18) ? s_ridx[m] : 0x7fffffff;
            #pragma unroll
            for (int o = 16; o; o >>= 1) {
                float ov = __shfl_down_sync(0xffffffffu, rv, o);
                int   oi = __shfl_down_sync(0xffffffffu, ri, o);
                if (ov > rv || (ov == rv && oi < ri)) { rv = ov; ri = oi; }
            }
            if (m == 0) { s_best = ri; s_order[k] = ri; s_sel[ri] = 1; }
        }
        __syncthreads();
        int best = s_best;

        float old = s_curmax[m];
        float nv = sim[(size_t)best * NTOK + m];
        bool ch = nv > old;
        unsigned bmask = __ballot_sync(0xffffffffu, ch);
        if (lane == 0) s_wcnt[w] = __popc(bmask);
        if (ch) s_curmax[m] = nv;
        __syncthreads();
        int base = 0, tot = 0;
        #pragma unroll
        for (int i = 0; i < 18; i++) { int cc = s_wcnt[i]; if (i < w) base += cc; tot += cc; }
        if (ch) {
            int pos = base + __popc(bmask & ((1u << lane) - 1u));
            s_chidx[pos] = (short)m;
            s_chold[pos] = old;
            s_chnew[pos] = nv;
        }
        __syncthreads();

        int r = 0;
        while (r + 4 <= tot) {
            int n0 = s_chidx[r + 0], n1 = s_chidx[r + 1], n2 = s_chidx[r + 2], n3 = s_chidx[r + 3];
            float o0 = s_chold[r + 0], o1 = s_chold[r + 1], o2 = s_chold[r + 2], o3 = s_chold[r + 3];
            float e0 = s_chnew[r + 0], e1 = s_chnew[r + 1], e2 = s_chnew[r + 2], e3 = s_chnew[r + 3];
            float v0 = sim[(size_t)n0 * NTOK + m];
            float v1 = sim[(size_t)n1 * NTOK + m];
            float v2 = sim[(size_t)n2 * NTOK + m];
            float v3 = sim[(size_t)n3 * NTOK + m];
            float d0 = fmaxf(__fsub_rn(fminf(v0, e0), o0), 0.f);
            float d1 = fmaxf(__fsub_rn(fminf(v1, e1), o1), 0.f);
            float d2 = fmaxf(__fsub_rn(fminf(v2, e2), o2), 0.f);
            float d3 = fmaxf(__fsub_rn(fminf(v3, e3), o3), 0.f);
            kacc(sum0, c0, -d0); kacc(sum1, c1, -d1);
            kacc(sum0, c0, -d2); kacc(sum1, c1, -d3);
            r += 4;
        }
        while (r < tot) {
            int nn = s_chidx[r];
            float oo = s_chold[r], ee = s_chnew[r];
            float vv = sim[(size_t)nn * NTOK + m];
            float dd = fmaxf(__fsub_rn(fminf(vv, ee), oo), 0.f);
            kacc(sum0, c0, -dd);
            r += 1;
        }
        __syncthreads();
    }

    bool f = s_sel[m] != 0;
    unsigned fm = __ballot_sync(0xffffffffu, f);
    if (lane == 0) s_wcnt[w] = __popc(fm);
    __syncthreads();
    int base = 0;
    #pragma unroll
    for (int i = 0; i < 18; i++) if (i < w) base += s_wcnt[i];
    if (f) g_sorted[b * KSEL + base + __popc(fm & ((1u << lane) - 1u))] = m + 1;
    if (m < KSEL) g_order[b * KSEL + m] = s_order[m] + 1;
}

// ---------------------------------------------------------------------------
// K4: gather dominant tokens + write selection-order indices (as float)
// ---------------------------------------------------------------------------
__global__ __launch_bounds__(128) void k_gather(const float* __restrict__ hidden,
                                                float* __restrict__ out_tok,
                                                float* __restrict__ out_idx,
                                                int write_idx) {
    int k = blockIdx.x, b = blockIdx.y;
    int gi = g_sorted[b * KSEL + k];
    const float4* src = (const float4*)(hidden + ((size_t)b * (NTOK + 1) + gi) * DD);
    float4* dst = (float4*)(out_tok + ((size_t)b * KSEL + k) * DD);
    int tid = threadIdx.x;
    dst[tid] = src[tid];
    dst[tid + 128] = src[tid + 128];
    if (write_idx && k == 0) out_idx[b * KSEL + tid] = (float)g_order[b * KSEL + tid];
}

// ---------------------------------------------------------------------------
extern "C" void kernel_launch(void* const* d_in, const int* in_sizes, int n_in,
                              void* d_out, int out_size) {
    const float* hidden = (const float*)d_in[0];   // [32, 577, 1024] f32
    const float* cls    = (const float*)d_in[1];   // [32, 576] f32
    float* out = (float*)d_out;

    k_normsplit<<<dim3(NTOK, BB), 256>>>(hidden);
    k_simgemm_tc<<<dim3(21, BB), 192>>>();
    k_greedy<<<BB, NTOK>>>(cls);

    const int tok_elems = BB * KSEL * DD;
    int write_idx = (out_size >= tok_elems + BB * KSEL) ? 1 : 0;
    k_gather<<<dim3(KSEL, BB), 128>>>(hidden, out, out + tok_elems, write_idx);
}

// round 14
// speedup vs baseline: 1.0725x; 1.0699x over previous
#include <cuda_runtime.h>
#include <cuda_fp16.h>
#include <cuda_pipeline.h>
#include <mma.h>
#include <math.h>
#include <float.h>

#define BB 32
#define NTOK 576
#define DD 1024
#define KSEL 128

using namespace nvcuda;

// Scratch (no cudaMalloc allowed)
__device__ __half g_h[BB * NTOK * DD];    // fp16 hi part of normalized feats
__device__ __half g_l[BB * NTOK * DD];    // fp16 lo part, scaled by 2048
__device__ float  g_sim[BB * NTOK * NTOK];
__device__ int    g_sorted[BB * KSEL];
__device__ int    g_order[BB * KSEL];

// ---------------------------------------------------------------------------
// K1: row-normalize feats = hidden[:,1:,:], split into fp16 hi/lo
// ---------------------------------------------------------------------------
__global__ __launch_bounds__(256) void k_normsplit(const float* __restrict__ hidden) {
    int n = blockIdx.x, b = blockIdx.y;
    const float4* src = (const float4*)(hidden + ((size_t)b * (NTOK + 1) + n + 1) * DD);
    int tid = threadIdx.x;
    float4 x = src[tid];
    float s = x.x * x.x + x.y * x.y + x.z * x.z + x.w * x.w;
    #pragma unroll
    for (int o = 16; o; o >>= 1) s += __shfl_xor_sync(0xffffffffu, s, o);
    __shared__ float sw[8];
    __shared__ float snrm;
    if ((tid & 31) == 0) sw[tid >> 5] = s;
    __syncthreads();
    if (tid == 0) {
        float t = 0.f;
        #pragma unroll
        for (int i = 0; i < 8; i++) t += sw[i];
        snrm = __fsqrt_rn(t);
    }
    __syncthreads();
    float nr = snrm;
    float y0 = __fdiv_rn(x.x, nr);
    float y1 = __fdiv_rn(x.y, nr);
    float y2 = __fdiv_rn(x.z, nr);
    float y3 = __fdiv_rn(x.w, nr);
    __half h0 = __float2half_rn(y0);
    __half h1 = __float2half_rn(y1);
    __half h2 = __float2half_rn(y2);
    __half h3 = __float2half_rn(y3);
    __half l0 = __float2half_rn(__fmul_rn(__fsub_rn(y0, __half2float(h0)), 2048.0f));
    __half l1 = __float2half_rn(__fmul_rn(__fsub_rn(y1, __half2float(h1)), 2048.0f));
    __half l2 = __float2half_rn(__fmul_rn(__fsub_rn(y2, __half2float(h2)), 2048.0f));
    __half l3 = __float2half_rn(__fmul_rn(__fsub_rn(y3, __half2float(h3)), 2048.0f));
    size_t base = ((size_t)b * NTOK + n) * DD;
    __half2* H2 = (__half2*)(g_h + base);
    __half2* L2 = (__half2*)(g_l + base);
    H2[tid * 2 + 0] = __halves2half2(h0, h1);
    H2[tid * 2 + 1] = __halves2half2(h2, h3);
    L2[tid * 2 + 0] = __halves2half2(l0, l1);
    L2[tid * 2 + 1] = __halves2half2(l2, l3);
}

// ---------------------------------------------------------------------------
// K2: sim[b] = H@H^T + 2^-11 (H@L^T + L@H^T), WMMA fp16 -> fp32 (no inline asm).
// CTA tile 96x96 (576 = 6*96), symmetric ti<=tj + mirror store.
// 6 warps (3x2), warp tile 32x48 = 2x3 wmma 16x16x16 tiles.
// k-chunk 16, double-buffered via __pipeline_memcpy_async.
// 2 CTAs/SM target via __launch_bounds__(192, 2); b-frags loaded inside the
// nt loop to lower live register count.
// ---------------------------------------------------------------------------
#define SARR 2304   // 96*24 halves per array
#define SLD  24     // smem leading dim in halves

__device__ __forceinline__ void load_chunk16(__half* sb,
                                             const __half* Hb, const __half* Lb,
                                             int i0, int j0, int k0, int tid) {
    int row = tid >> 1;
    int seg = tid & 1;
    size_t goffA = (size_t)(i0 + row) * DD + k0 + seg * 8;
    size_t goffB = (size_t)(j0 + row) * DD + k0 + seg * 8;
    int soff = row * SLD + seg * 8;
    __pipeline_memcpy_async(sb + 0 * SARR + soff, Hb + goffA, 16);
    __pipeline_memcpy_async(sb + 1 * SARR + soff, Lb + goffA, 16);
    __pipeline_memcpy_async(sb + 2 * SARR + soff, Hb + goffB, 16);
    __pipeline_memcpy_async(sb + 3 * SARR + soff, Lb + goffB, 16);
    __pipeline_commit();
}

__global__ __launch_bounds__(192, 2) void k_simgemm_tc() {
    int b = blockIdx.y;
    int t = blockIdx.x;                 // 0..20 -> (ti<=tj) over 6x6 tiles
    int ti = 0, rem = 6;
    while (t >= rem) { t -= rem; rem--; ti++; }
    int tj = ti + t;
    int i0 = ti * 96, j0 = tj * 96;

    const __half* Hb = g_h + (size_t)b * NTOK * DD;
    const __half* Lb = g_l + (size_t)b * NTOK * DD;
    float* C = g_sim + (size_t)b * NTOK * NTOK;

    __shared__ __half sm[2][4 * SARR];   // 2 stages x 4 arrays, 36864 bytes

    int tid = threadIdx.x;
    int warp = tid >> 5;
    int wm = (warp % 3) * 32;            // M offset within 96
    int wn = (warp / 3) * 48;            // N offset within 96

    wmma::fragment<wmma::accumulator, 16, 16, 16, float> acc0[2][3];
    wmma::fragment<wmma::accumulator, 16, 16, 16, float> acc1[2][3];
    #pragma unroll
    for (int mt = 0; mt < 2; mt++) {
        #pragma unroll
        for (int nt = 0; nt < 3; nt++) {
            wmma::fill_fragment(acc0[mt][nt], 0.0f);
            wmma::fill_fragment(acc1[mt][nt], 0.0f);
        }
    }

    load_chunk16(&sm[0][0], Hb, Lb, i0, j0, 0, tid);

    const int NCHUNK = DD / 16;   // 64
    for (int ck = 0; ck < NCHUNK; ck++) {
        int st = ck & 1;
        if (ck + 1 < NCHUNK) {
            load_chunk16(&sm[st ^ 1][0], Hb, Lb, i0, j0, (ck + 1) * 16, tid);
            __pipeline_wait_prior(1);
        } else {
            __pipeline_wait_prior(0);
        }
        __syncthreads();

        __half* base = &sm[st][0];
        wmma::fragment<wmma::matrix_a, 16, 16, 16, __half, wmma::row_major> aH[2], aL[2];
        #pragma unroll
        for (int mt = 0; mt < 2; mt++) {
            wmma::load_matrix_sync(aH[mt], base + 0 * SARR + (wm + mt * 16) * SLD, SLD);
            wmma::load_matrix_sync(aL[mt], base + 1 * SARR + (wm + mt * 16) * SLD, SLD);
        }
        #pragma unroll
        for (int nt = 0; nt < 3; nt++) {
            wmma::fragment<wmma::matrix_b, 16, 16, 16, __half, wmma::col_major> bH, bL;
            wmma::load_matrix_sync(bH, base + 2 * SARR + (wn + nt * 16) * SLD, SLD);
            wmma::load_matrix_sync(bL, base + 3 * SARR + (wn + nt * 16) * SLD, SLD);
            #pragma unroll
            for (int mt = 0; mt < 2; mt++) {
                wmma::mma_sync(acc0[mt][nt], aH[mt], bH, acc0[mt][nt]);
                wmma::mma_sync(acc1[mt][nt], aH[mt], bL, acc1[mt][nt]);
                wmma::mma_sync(acc1[mt][nt], aL[mt], bH, acc1[mt][nt]);
            }
        }
        __syncthreads();
    }

    const float S = 4.8828125e-4f;   // 2^-11
    #pragma unroll
    for (int mt = 0; mt < 2; mt++) {
        #pragma unroll
        for (int nt = 0; nt < 3; nt++) {
            #pragma unroll
            for (int e = 0; e < acc0[mt][nt].num_elements; e++) {
                acc0[mt][nt].x[e] = acc0[mt][nt].x[e] + acc1[mt][nt].x[e] * S;
            }
            int r0 = i0 + wm + mt * 16;
            int c0 = j0 + wn + nt * 16;
            wmma::store_matrix_sync(&C[(size_t)r0 * NTOK + c0], acc0[mt][nt],
                                    NTOK, wmma::mem_row_major);
            if (ti != tj) {
                wmma::store_matrix_sync(&C[(size_t)c0 * NTOK + r0], acc0[mt][nt],
                                        NTOK, wmma::mem_col_major);
            }
        }
    }
}

// ---------------------------------------------------------------------------
// K3: greedy SCOPE selection, one CTA per batch, incremental gain updates.
// Unroll-8 update loop (bit-identical accumulator pairing vs unroll-4),
// redundant end-of-iteration barrier removed.
// ---------------------------------------------------------------------------
__device__ __forceinline__ void kacc(float& s, float& c, float x) {
    float y = __fsub_rn(x, c);
    float t = __fadd_rn(s, y);
    c = __fsub_rn(__fsub_rn(t, s), y);
    s = t;
}

__global__ __launch_bounds__(NTOK) void k_greedy(const float* __restrict__ cls_attn) {
    int b = blockIdx.x;
    const float* sim = g_sim + (size_t)b * NTOK * NTOK;
    int m = threadIdx.x;
    int w = m >> 5, lane = m & 31;

    __shared__ float s_curmax[NTOK];
    __shared__ float s_cls[NTOK];
    __shared__ unsigned char s_sel[NTOK];
    __shared__ short s_chidx[NTOK];
    __shared__ float s_chold[NTOK];
    __shared__ float s_chnew[NTOK];
    __shared__ int s_wcnt[18];
    __shared__ float s_rval[18];
    __shared__ int s_ridx[18];
    __shared__ int s_best;
    __shared__ int s_order[KSEL];

    s_cls[m] = cls_attn[b * NTOK + m];
    s_curmax[m] = 0.f;
    s_sel[m] = 0;

    float sum0 = 0.f, c0 = 0.f, sum1 = 0.f, c1 = 0.f;
    for (int n = 0; n < NTOK; n += 8) {
        float v[8];
        #pragma unroll
        for (int u = 0; u < 8; u++) v[u] = sim[(size_t)(n + u) * NTOK + m];
        #pragma unroll
        for (int u = 0; u < 8; u++) {
            float rl = fmaxf(v[u], 0.f);
            if (u & 1) kacc(sum1, c1, rl); else kacc(sum0, c0, rl);
        }
    }
    __syncthreads();

    for (int k = 0; k < KSEL; k++) {
        float g = __fadd_rn(__fsub_rn(sum0, c0), __fsub_rn(sum1, c1));
        float key = s_sel[m] ? -FLT_MAX : g * s_cls[m];
        float bv = key; int bi = m;
        #pragma unroll
        for (int o = 16; o; o >>= 1) {
            float ov = __shfl_down_sync(0xffffffffu, bv, o);
            int   oi = __shfl_down_sync(0xffffffffu, bi, o);
            if (ov > bv || (ov == bv && oi < bi)) { bv = ov; bi = oi; }
        }
        if (lane == 0) { s_rval[w] = bv; s_ridx[w] = bi; }
        __syncthreads();                                   // S1
        if (m < 32) {
            float rv = (m < 18) ? s_rval[m] : -FLT_MAX;
            int   ri = (m < 18) ? s_ridx[m] : 0x7fffffff;
            #pragma unroll
            for (int o = 16; o; o >>= 1) {
                float ov = __shfl_down_sync(0xffffffffu, rv, o);
                int   oi = __shfl_down_sync(0xffffffffu, ri, o);
                if (ov > rv || (ov == rv && oi < ri)) { rv = ov; ri = oi; }
            }
            if (m == 0) { s_best = ri; s_order[k] = ri; s_sel[ri] = 1; }
        }
        __syncthreads();                                   // S2
        int best = s_best;

        float old = s_curmax[m];
        float nv = sim[(size_t)best * NTOK + m];
        bool ch = nv > old;
        unsigned bmask = __ballot_sync(0xffffffffu, ch);
        if (lane == 0) s_wcnt[w] = __popc(bmask);
        if (ch) s_curmax[m] = nv;
        __syncthreads();                                   // S3
        int base = 0, tot = 0;
        #pragma unroll
        for (int i = 0; i < 18; i++) { int cc = s_wcnt[i]; if (i < w) base += cc; tot += cc; }
        if (ch) {
            int pos = base + __popc(bmask & ((1u << lane) - 1u));
            s_chidx[pos] = (short)m;
            s_chold[pos] = old;
            s_chnew[pos] = nv;
        }
        __syncthreads();                                   // S4

        int r = 0;
        while (r + 8 <= tot) {
            short nn[8]; float oo[8], ee[8], vv[8], dd[8];
            #pragma unroll
            for (int u = 0; u < 8; u++) { nn[u] = s_chidx[r + u]; oo[u] = s_chold[r + u]; ee[u] = s_chnew[r + u]; }
            #pragma unroll
            for (int u = 0; u < 8; u++) vv[u] = sim[(size_t)nn[u] * NTOK + m];
            #pragma unroll
            for (int u = 0; u < 8; u++) dd[u] = fmaxf(__fsub_rn(fminf(vv[u], ee[u]), oo[u]), 0.f);
            kacc(sum0, c0, -dd[0]); kacc(sum1, c1, -dd[1]);
            kacc(sum0, c0, -dd[2]); kacc(sum1, c1, -dd[3]);
            kacc(sum0, c0, -dd[4]); kacc(sum1, c1, -dd[5]);
            kacc(sum0, c0, -dd[6]); kacc(sum1, c1, -dd[7]);
            r += 8;
        }
        while (r + 4 <= tot) {
            int n0 = s_chidx[r + 0], n1 = s_chidx[r + 1], n2 = s_chidx[r + 2], n3 = s_chidx[r + 3];
            float o0 = s_chold[r + 0], o1 = s_chold[r + 1], o2 = s_chold[r + 2], o3 = s_chold[r + 3];
            float e0 = s_chnew[r + 0], e1 = s_chnew[r + 1], e2 = s_chnew[r + 2], e3 = s_chnew[r + 3];
            float v0 = sim[(size_t)n0 * NTOK + m];
            float v1 = sim[(size_t)n1 * NTOK + m];
            float v2 = sim[(size_t)n2 * NTOK + m];
            float v3 = sim[(size_t)n3 * NTOK + m];
            float d0 = fmaxf(__fsub_rn(fminf(v0, e0), o0), 0.f);
            float d1 = fmaxf(__fsub_rn(fminf(v1, e1), o1), 0.f);
            float d2 = fmaxf(__fsub_rn(fminf(v2, e2), o2), 0.f);
            float d3 = fmaxf(__fsub_rn(fminf(v3, e3), o3), 0.f);
            kacc(sum0, c0, -d0); kacc(sum1, c1, -d1);
            kacc(sum0, c0, -d2); kacc(sum1, c1, -d3);
            r += 4;
        }
        while (r < tot) {
            int nn = s_chidx[r];
            float oo = s_chold[r], ee = s_chnew[r];
            float vv = sim[(size_t)nn * NTOK + m];
            float dd = fmaxf(__fsub_rn(fminf(vv, ee), oo), 0.f);
            kacc(sum0, c0, -dd);
            r += 1;
        }
        // no barrier here: next-iteration hazards are covered by S1..S4
    }

    __syncthreads();
    bool f = s_sel[m] != 0;
    unsigned fm = __ballot_sync(0xffffffffu, f);
    if (lane == 0) s_wcnt[w] = __popc(fm);
    __syncthreads();
    int base = 0;
    #pragma unroll
    for (int i = 0; i < 18; i++) if (i < w) base += s_wcnt[i];
    if (f) g_sorted[b * KSEL + base + __popc(fm & ((1u << lane) - 1u))] = m + 1;
    if (m < KSEL) g_order[b * KSEL + m] = s_order[m] + 1;
}

// ---------------------------------------------------------------------------
// K4: gather dominant tokens + write selection-order indices (as float)
// ---------------------------------------------------------------------------
__global__ __launch_bounds__(128) void k_gather(const float* __restrict__ hidden,
                                                float* __restrict__ out_tok,
                                                float* __restrict__ out_idx,
                                                int write_idx) {
    int k = blockIdx.x, b = blockIdx.y;
    int gi = g_sorted[b * KSEL + k];
    const float4* src = (const float4*)(hidden + ((size_t)b * (NTOK + 1) + gi) * DD);
    float4* dst = (float4*)(out_tok + ((size_t)b * KSEL + k) * DD);
    int tid = threadIdx.x;
    dst[tid] = src[tid];
    dst[tid + 128] = src[tid + 128];
    if (write_idx && k == 0) out_idx[b * KSEL + tid] = (float)g_order[b * KSEL + tid];
}

// ---------------------------------------------------------------------------
extern "C" void kernel_launch(void* const* d_in, const int* in_sizes, int n_in,
                              void* d_out, int out_size) {
    const float* hidden = (const float*)d_in[0];   // [32, 577, 1024] f32
    const float* cls    = (const float*)d_in[1];   // [32, 576] f32
    float* out = (float*)d_out;

    k_normsplit<<<dim3(NTOK, BB), 256>>>(hidden);
    k_simgemm_tc<<<dim3(21, BB), 192>>>();
    k_greedy<<<BB, NTOK>>>(cls);

    const int tok_elems = BB * KSEL * DD;
    int write_idx = (out_size >= tok_elems + BB * KSEL) ? 1 : 0;
    k_gather<<<dim3(KSEL, BB), 128>>>(hidden, out, out + tok_elems, write_idx);
}